// round 5
// baseline (speedup 1.0000x reference)
#include <cuda_runtime.h>
#include <math.h>
#include <stdint.h>

#define N_NODES 100000
#define N_RELS  500
#define DIMV    200
#define N_EDG   200000
#define NP1     640   // P1 row stride: [A1 | L1 | Graw | pad]
#define NP2     448   // P2 row stride: [A2 | L2 | pad]
#define BM      128
#define NT1     10    // 640/64
#define NT2     7     // 448/64
#define AFRAG   25600 // 8 mblk * 25 ks * 32 lane * 4
#define BTILE   12800 // 25 ks * 64 col * 8
#define SMEMB   ((AFRAG + 2 * BTILE) * 4)   // 204800 B

// ---------------- scratch (device globals; no allocation allowed) ----------
__device__ float g_h  [(size_t)N_NODES * DIMV];
__device__ float g_r  [(size_t)N_RELS  * DIMV];
__device__ float g_P1 [(size_t)N_NODES * NP1];
__device__ float g_P2 [(size_t)N_NODES * NP2];
__device__ float g_agg1[(size_t)N_NODES * DIMV];
__device__ float g_agg2[(size_t)N_NODES * DIMV];
__device__ float g_rA1[(size_t)N_RELS * DIMV];
__device__ float g_rA2[(size_t)N_RELS * DIMV];
__device__ float g_W1fm[NT1 * BTILE];   // frag-major tf32 [Wm1|Wl1|Wg]
__device__ float g_W2fm[NT2 * BTILE];   // frag-major tf32 [Wm2|Wl2]
__device__ float g_deg[N_NODES];

// ---------------- helpers ---------------------------------------------------
__device__ __forceinline__ float to_tf32(float x) {
    float y;
    asm("cvt.rna.tf32.f32 %0, %1;" : "=f"(y) : "f"(x));
    return y;
}

__device__ __forceinline__ void mma8(float* c, const uint32_t* a, const uint32_t* b) {
    asm volatile(
        "mma.sync.aligned.m16n8k8.row.col.f32.tf32.tf32.f32 "
        "{%0,%1,%2,%3},{%4,%5,%6,%7},{%8,%9},{%0,%1,%2,%3};"
        : "+f"(c[0]), "+f"(c[1]), "+f"(c[2]), "+f"(c[3])
        : "r"(a[0]), "r"(a[1]), "r"(a[2]), "r"(a[3]), "r"(b[0]), "r"(b[1]));
}

__device__ __forceinline__ void cpa16(void* sdst, const void* gsrc) {
    uint32_t s = (uint32_t)__cvta_generic_to_shared(sdst);
    asm volatile("cp.async.cg.shared.global [%0], [%1], 16;" :: "r"(s), "l"(gsrc));
}
#define CP_COMMIT() asm volatile("cp.async.commit_group;")
#define CP_WAIT0()  asm volatile("cp.async.wait_group 0;")

// ---------------- small utility kernels ------------------------------------
__global__ void zero4_kernel(float4* __restrict__ p, int n4) {
    int i = blockIdx.x * blockDim.x + threadIdx.x;
    if (i < n4) p[i] = make_float4(0.f, 0.f, 0.f, 0.f);
}

__global__ void l2norm_kernel(const float* __restrict__ in, float* __restrict__ out, int rows) {
    int warp = (blockIdx.x * blockDim.x + threadIdx.x) >> 5;
    int lane = threadIdx.x & 31;
    if (warp >= rows) return;
    const float* p = in + (size_t)warp * DIMV;
    float s = 0.f;
    #pragma unroll
    for (int i = 0; i < 7; i++) {
        int j = lane + i * 32;
        float v = (j < DIMV) ? p[j] : 0.f;
        s += v * v;
    }
    #pragma unroll
    for (int o = 16; o; o >>= 1) s += __shfl_xor_sync(0xffffffffu, s, o);
    float inv = 1.f / fmaxf(sqrtf(s), 1e-12f);
    float* q = out + (size_t)warp * DIMV;
    #pragma unroll
    for (int i = 0; i < 7; i++) {
        int j = lane + i * 32;
        if (j < DIMV) q[j] = p[j] * inv;
    }
}

__global__ void deg_kernel(const int* __restrict__ e, float* __restrict__ deg) {
    int i = blockIdx.x * blockDim.x + threadIdx.x;
    if (i < N_EDG) atomicAdd(&deg[e[3 * i + 2]], 1.0f);
}

// pack weights into fragment-major tf32 layout:
// out[((nt*25+ks)*64 + c)*8 + t*2+half] = tf32(W[ks*8+t+half*4][nt*64+c])
__global__ void packW1fm_kernel(const float* __restrict__ Wa, const float* __restrict__ Wb,
                                const float* __restrict__ Wc, float* __restrict__ out) {
    int idx = blockIdx.x * blockDim.x + threadIdx.x;
    if (idx >= NT1 * BTILE) return;
    int nt = idx / BTILE, rem = idx % BTILE;
    int ks = rem / 512, rem2 = rem % 512;
    int c = rem2 >> 3, e = rem2 & 7;
    int t = e >> 1, half = e & 1;
    int k = ks * 8 + t + half * 4;
    int n = nt * 64 + c;
    float v = 0.f;
    if (n < 200)      v = Wa[k * 200 + n];
    else if (n < 400) v = Wb[k * 200 + n - 200];
    else if (n < 600) v = Wc[k * 200 + n - 400];
    out[idx] = to_tf32(v);
}

__global__ void packW2fm_kernel(const float* __restrict__ Wa, const float* __restrict__ Wb,
                                float* __restrict__ out) {
    int idx = blockIdx.x * blockDim.x + threadIdx.x;
    if (idx >= NT2 * BTILE) return;
    int nt = idx / BTILE, rem = idx % BTILE;
    int ks = rem / 512, rem2 = rem % 512;
    int c = rem2 >> 3, e = rem2 & 7;
    int t = e >> 1, half = e & 1;
    int k = ks * 8 + t + half * 4;
    int n = nt * 64 + c;
    float v = 0.f;
    if (n < 200)      v = Wa[k * 200 + n];
    else if (n < 400) v = Wb[k * 200 + n - 200];
    out[idx] = to_tf32(v);
}

// warp-per-edge scatter; red.global (no return) vectorized
__global__ void scatter_kernel(const int* __restrict__ e,
                               const float* __restrict__ A, int astr,
                               const float* __restrict__ rA,
                               float* __restrict__ agg) {
    int warp = (blockIdx.x * blockDim.x + threadIdx.x) >> 5;
    int lane = threadIdx.x & 31;
    if (warp >= N_EDG) return;
    int src = e[3 * warp + 0];
    int rel = e[3 * warp + 1];
    int dst = e[3 * warp + 2];
    const float4* a  = (const float4*)(A  + (size_t)src * astr);
    const float4* ra = (const float4*)(rA + (size_t)rel * DIMV);
    float4*       d  = (float4*)(agg + (size_t)dst * DIMV);
    #pragma unroll 2
    for (int c = lane; c < DIMV / 4; c += 32) {
        float4 va = a[c], vr = ra[c];
        float4 v = make_float4(va.x + vr.x, va.y + vr.y, va.z + vr.z, va.w + vr.w);
        asm volatile("red.global.add.v4.f32 [%0], {%1,%2,%3,%4};"
                     :: "l"(d + c), "f"(v.x), "f"(v.y), "f"(v.z), "f"(v.w)
                     : "memory");
    }
}

// ---------------- tf32 MMA GEMM with frag-major SMEM + cp.async dbuf -------
// Out[M, NT*64] = A[M,200] @ Bfm(packed frag-major weights)
// AFILL 0: A = Asrc; AFILL 1: A = Asrc + agg/max(deg,1)
template <int AFILL>
__global__ void __launch_bounds__(256)
mma_gemm(const float* __restrict__ Asrc, int astride,
         const float* __restrict__ agg, const float* __restrict__ deg,
         const float* __restrict__ Bfm,
         float* __restrict__ Out, int ostride, int realN,
         int M, int NT) {
    extern __shared__ float smf[];
    float* As = smf;             // AFRAG floats, fragment-major
    float* Bs = smf + AFRAG;     // 2 * BTILE floats
    const int tid  = threadIdx.x;
    const int row0 = blockIdx.x * BM;

    // ---- A fill: gmem -> tf32 fragment-major SMEM (once) ----
    {
        int r = tid >> 1;                 // 0..127 local row
        int cbase = (tid & 1) * 100;
        int grow = row0 + r;
        bool valid = grow < M;
        float invd = 1.f;
        if (AFILL == 1 && valid) invd = 1.f / fmaxf(deg[grow], 1.f);
        const float* ap = Asrc + (size_t)grow * astride;
        const float* gp = agg + (size_t)grow * DIMV;
        int mblk = r >> 4, rr = r & 15, gidr = rr & 7, half = rr >> 3;
        #pragma unroll
        for (int i = 0; i < 25; i++) {
            int c = cbase + i * 4;
            float4 v = make_float4(0.f, 0.f, 0.f, 0.f);
            if (valid) {
                v = *(const float4*)(ap + c);
                if (AFILL == 1) {
                    float4 g4 = *(const float4*)(gp + c);
                    v.x += g4.x * invd; v.y += g4.y * invd;
                    v.z += g4.z * invd; v.w += g4.w * invd;
                }
            }
            int ks = c >> 3;
            int khalf = (c & 7) >> 2;     // c%4==0 -> kk is 0 or 4
            float* dst = As + ((mblk * 25 + ks) * 32 + gidr * 4) * 4 + khalf * 2 + half;
            dst[0]  = to_tf32(v.x);
            dst[4]  = to_tf32(v.y);
            dst[8]  = to_tf32(v.z);
            dst[12] = to_tf32(v.w);
        }
    }

    // ---- prefetch B tile 0 ----
    {
        const float4* src = (const float4*)Bfm;
        float4* dst = (float4*)Bs;
        for (int i = tid; i < BTILE / 4; i += 256) cpa16(dst + i, src + i);
        CP_COMMIT();
    }
    __syncthreads();   // A fill visible

    const int wid = tid >> 5, lane = tid & 31;
    const int gid = lane >> 2, tig = lane & 3;
    const int wm16 = (wid >> 1) * 2;  // mblk base
    const int wm   = wm16 * 16;       // warp m offset
    const int wn   = (wid & 1) * 32;  // warp n offset
    const float4* As4 = (const float4*)As;

    for (int nt = 0; nt < NT; nt++) {
        CP_WAIT0();
        __syncthreads();
        if (nt + 1 < NT) {
            const float4* src = (const float4*)(Bfm + (size_t)(nt + 1) * BTILE);
            float4* dst = (float4*)(Bs + ((nt + 1) & 1) * BTILE);
            for (int i = tid; i < BTILE / 4; i += 256) cpa16(dst + i, src + i);
            CP_COMMIT();
        }
        const float2* B2 = (const float2*)(Bs + (nt & 1) * BTILE);

        float acc[2][4][4];
        #pragma unroll
        for (int mi = 0; mi < 2; mi++)
            #pragma unroll
            for (int ni = 0; ni < 4; ni++)
                #pragma unroll
                for (int q = 0; q < 4; q++) acc[mi][ni][q] = 0.f;

        #pragma unroll
        for (int ks = 0; ks < 25; ks++) {
            uint32_t a[2][4], b[4][2];
            *(float4*)a[0] = As4[((wm16 + 0) * 25 + ks) * 32 + lane];
            *(float4*)a[1] = As4[((wm16 + 1) * 25 + ks) * 32 + lane];
            #pragma unroll
            for (int ni = 0; ni < 4; ni++)
                *(float2*)b[ni] = B2[(ks * 64 + wn + ni * 8 + gid) * 4 + tig];
            #pragma unroll
            for (int mi = 0; mi < 2; mi++)
                #pragma unroll
                for (int ni = 0; ni < 4; ni++)
                    mma8(acc[mi][ni], a[mi], b[ni]);
        }

        // ---- epilogue: masked strided stores ----
        int n0 = nt * 64;
        #pragma unroll
        for (int mi = 0; mi < 2; mi++) {
            #pragma unroll
            for (int ni = 0; ni < 4; ni++) {
                int grow = row0 + wm + mi * 16 + gid;
                int gcol = n0 + wn + ni * 8 + tig * 2;
                if (gcol < realN) {
                    if (grow < M)
                        *(float2*)(Out + (size_t)grow * ostride + gcol) =
                            make_float2(acc[mi][ni][0], acc[mi][ni][1]);
                    if (grow + 8 < M)
                        *(float2*)(Out + (size_t)(grow + 8) * ostride + gcol) =
                            make_float2(acc[mi][ni][2], acc[mi][ni][3]);
                }
            }
        }
    }
}

// ------- fused final: gate=sig(Graw+b); c2=L2raw+agg2/deg; h'=l2n(g*l2n(c2)+(1-g)h)
__global__ void final_kernel(const float* __restrict__ P1,
                             const float* __restrict__ bias,
                             const float* __restrict__ P2,
                             const float* __restrict__ agg2,
                             const float* __restrict__ deg,
                             const float* __restrict__ hin,
                             float* __restrict__ hout) {
    int warp = (blockIdx.x * blockDim.x + threadIdx.x) >> 5;
    int lane = threadIdx.x & 31;
    if (warp >= N_NODES) return;
    const float* graw = P1 + (size_t)warp * NP1 + 400;
    const float* l2r  = P2 + (size_t)warp * NP2 + 200;
    const float* ag   = agg2 + (size_t)warp * DIMV;
    const float* hp   = hin + (size_t)warp * DIMV;
    float invd = 1.f / fmaxf(deg[warp], 1.f);

    float cv[7], gv[7], hv[7];
    float s = 0.f;
    #pragma unroll
    for (int i = 0; i < 7; i++) {
        int j = lane + i * 32;
        float x = 0.f, g = 0.f, hh = 0.f;
        if (j < DIMV) {
            x  = l2r[j] + ag[j] * invd;
            g  = 1.f / (1.f + expf(-(graw[j] + bias[j])));
            hh = hp[j];
        }
        cv[i] = x; gv[i] = g; hv[i] = hh;
        s += x * x;
    }
    #pragma unroll
    for (int o = 16; o; o >>= 1) s += __shfl_xor_sync(0xffffffffu, s, o);
    float inv = 1.f / fmaxf(sqrtf(s), 1e-12f);

    float s2 = 0.f;
    #pragma unroll
    for (int i = 0; i < 7; i++) {
        float v = gv[i] * (cv[i] * inv) + (1.f - gv[i]) * hv[i];
        cv[i] = v;
        s2 += v * v;
    }
    #pragma unroll
    for (int o = 16; o; o >>= 1) s2 += __shfl_xor_sync(0xffffffffu, s2, o);
    float inv2 = 1.f / fmaxf(sqrtf(s2), 1e-12f);

    float* op = hout + (size_t)warp * DIMV;
    #pragma unroll
    for (int i = 0; i < 7; i++) {
        int j = lane + i * 32;
        if (j < DIMV) op[j] = cv[i] * inv2;
    }
}

// ---------------- host launcher --------------------------------------------
extern "C" void kernel_launch(void* const* d_in, const int* in_sizes, int n_in,
                              void* d_out, int out_size) {
    const int*   edges = (const int*)d_in[0];
    const float* ent   = (const float*)d_in[1];
    const float* rele  = (const float*)d_in[2];
    const float* Wm1   = (const float*)d_in[3];
    const float* Wl1   = (const float*)d_in[4];
    const float* Wm2   = (const float*)d_in[5];
    const float* Wl2   = (const float*)d_in[6];
    const float* Wg    = (const float*)d_in[7];
    const float* bg    = (const float*)d_in[8];
    float* out = (float*)d_out;

    float *h, *r, *P1, *P2, *agg1, *agg2, *rA1, *rA2, *W1fm, *W2fm, *deg;
    cudaGetSymbolAddress((void**)&h,    g_h);
    cudaGetSymbolAddress((void**)&r,    g_r);
    cudaGetSymbolAddress((void**)&P1,   g_P1);
    cudaGetSymbolAddress((void**)&P2,   g_P2);
    cudaGetSymbolAddress((void**)&agg1, g_agg1);
    cudaGetSymbolAddress((void**)&agg2, g_agg2);
    cudaGetSymbolAddress((void**)&rA1,  g_rA1);
    cudaGetSymbolAddress((void**)&rA2,  g_rA2);
    cudaGetSymbolAddress((void**)&W1fm, g_W1fm);
    cudaGetSymbolAddress((void**)&W2fm, g_W2fm);
    cudaGetSymbolAddress((void**)&deg,  g_deg);

    cudaFuncSetAttribute(mma_gemm<0>, cudaFuncAttributeMaxDynamicSharedMemorySize, SMEMB);
    cudaFuncSetAttribute(mma_gemm<1>, cudaFuncAttributeMaxDynamicSharedMemorySize, SMEMB);

    const int grid_m  = (N_NODES + BM - 1) / BM;  // 782
    const int grid_mr = (N_RELS + BM - 1) / BM;   // 4
    const int n_agg4  = (N_NODES * DIMV) / 4;
    const int n_deg4  = N_NODES / 4;

    l2norm_kernel<<<(N_NODES + 7) / 8, 256>>>(ent, h, N_NODES);
    l2norm_kernel<<<(N_RELS + 7) / 8, 256>>>(rele, r, N_RELS);
    packW1fm_kernel<<<(NT1 * BTILE + 255) / 256, 256>>>(Wm1, Wl1, Wg, W1fm);
    packW2fm_kernel<<<(NT2 * BTILE + 255) / 256, 256>>>(Wm2, Wl2, W2fm);

    // time-invariant: rA1 = r@Wm1, rA2 = r@Wm2 (cols 0..199 of packed weights)
    mma_gemm<0><<<grid_mr, 256, SMEMB>>>(r, DIMV, nullptr, nullptr, W1fm,
                                         rA1, DIMV, DIMV, N_RELS, 4);
    mma_gemm<0><<<grid_mr, 256, SMEMB>>>(r, DIMV, nullptr, nullptr, W2fm,
                                         rA2, DIMV, DIMV, N_RELS, 4);

    for (int t = 0; t < 3; t++) {
        const int* e = edges + (size_t)t * N_EDG * 3;

        zero4_kernel<<<(n_deg4 + 255) / 256, 256>>>((float4*)deg, n_deg4);
        deg_kernel<<<(N_EDG + 255) / 256, 256>>>(e, deg);
        zero4_kernel<<<(n_agg4 + 255) / 256, 256>>>((float4*)agg1, n_agg4);

        // P1 = h @ [Wm1 | Wl1 | Wg]
        mma_gemm<0><<<grid_m, 256, SMEMB>>>(h, DIMV, nullptr, nullptr, W1fm,
                                            P1, NP1, 600, N_NODES, NT1);
        scatter_kernel<<<(N_EDG + 7) / 8, 256>>>(e, P1, NP1, rA1, agg1);

        zero4_kernel<<<(n_agg4 + 255) / 256, 256>>>((float4*)agg2, n_agg4);
        // P2 = c1 @ [Wm2 | Wl2], c1 = L1 + agg1/deg computed in A-fill
        mma_gemm<1><<<grid_m, 256, SMEMB>>>(P1 + 200, NP1, agg1, deg, W2fm,
                                            P2, NP2, 400, N_NODES, NT2);
        scatter_kernel<<<(N_EDG + 7) / 8, 256>>>(e, P2, NP2, rA2, agg2);

        final_kernel<<<(N_NODES + 7) / 8, 256>>>(P1, bg, P2, agg2, deg, h,
                                                 (t == 2) ? out : h);
    }
}

// round 7
// speedup vs baseline: 1.3794x; 1.3794x over previous
#include <cuda_runtime.h>
#include <math.h>
#include <stdint.h>

#define N_NODES 100000
#define N_RELS  500
#define DIMV    200
#define N_EDG   200000
#define NP1     640   // P1 row stride: [A1 | L1 | Graw | pad]
#define NP2     448   // P2 row stride: [A2 | L2 | pad]
#define BM      64
#define NT1     10    // 640/64
#define NT2     7     // 448/64
#define BTILE   12800 // 25 ks * 64 col * 8 (frag-major floats per 64-col tile)
#define SMEMB   (2 * BTILE * 4)   // 102400 B -> 2 CTAs/SM

// ---------------- scratch (device globals; no allocation allowed) ----------
__device__ float g_h  [(size_t)N_NODES * DIMV];
__device__ float g_r  [(size_t)N_RELS  * DIMV];
__device__ float g_P1 [(size_t)N_NODES * NP1];
__device__ float g_P2 [(size_t)N_NODES * NP2];
__device__ float g_agg1[(size_t)N_NODES * DIMV];
__device__ float g_agg2[(size_t)N_NODES * DIMV];
__device__ float g_rA1[(size_t)N_RELS * DIMV];
__device__ float g_rA2[(size_t)N_RELS * DIMV];
__device__ float g_W1fm[NT1 * BTILE];   // frag-major tf32 [Wm1|Wl1|Wg]
__device__ float g_W2fm[NT2 * BTILE];   // frag-major tf32 [Wm2|Wl2]
__device__ float g_deg[N_NODES];

// ---------------- helpers ---------------------------------------------------
__device__ __forceinline__ float to_tf32(float x) {
    float y;
    asm("cvt.rna.tf32.f32 %0, %1;" : "=f"(y) : "f"(x));
    return y;
}

__device__ __forceinline__ void mma8(float* c, const uint32_t* a, const uint32_t* b) {
    asm volatile(
        "mma.sync.aligned.m16n8k8.row.col.f32.tf32.tf32.f32 "
        "{%0,%1,%2,%3},{%4,%5,%6,%7},{%8,%9},{%0,%1,%2,%3};"
        : "+f"(c[0]), "+f"(c[1]), "+f"(c[2]), "+f"(c[3])
        : "r"(a[0]), "r"(a[1]), "r"(a[2]), "r"(a[3]), "r"(b[0]), "r"(b[1]));
}

__device__ __forceinline__ void cpa16(void* sdst, const void* gsrc) {
    uint32_t s = (uint32_t)__cvta_generic_to_shared(sdst);
    asm volatile("cp.async.cg.shared.global [%0], [%1], 16;" :: "r"(s), "l"(gsrc));
}
#define CP_COMMIT() asm volatile("cp.async.commit_group;")
#define CP_WAIT0()  asm volatile("cp.async.wait_group 0;")

// ---------------- small utility kernels ------------------------------------
__global__ void zero4_kernel(float4* __restrict__ p, int n4) {
    int i = blockIdx.x * blockDim.x + threadIdx.x;
    if (i < n4) p[i] = make_float4(0.f, 0.f, 0.f, 0.f);
}

__global__ void l2norm_kernel(const float* __restrict__ in, float* __restrict__ out, int rows) {
    int warp = (blockIdx.x * blockDim.x + threadIdx.x) >> 5;
    int lane = threadIdx.x & 31;
    if (warp >= rows) return;
    const float* p = in + (size_t)warp * DIMV;
    float s = 0.f;
    #pragma unroll
    for (int i = 0; i < 7; i++) {
        int j = lane + i * 32;
        float v = (j < DIMV) ? p[j] : 0.f;
        s += v * v;
    }
    #pragma unroll
    for (int o = 16; o; o >>= 1) s += __shfl_xor_sync(0xffffffffu, s, o);
    float inv = 1.f / fmaxf(sqrtf(s), 1e-12f);
    float* q = out + (size_t)warp * DIMV;
    #pragma unroll
    for (int i = 0; i < 7; i++) {
        int j = lane + i * 32;
        if (j < DIMV) q[j] = p[j] * inv;
    }
}

__global__ void deg_kernel(const int* __restrict__ e, float* __restrict__ deg) {
    int i = blockIdx.x * blockDim.x + threadIdx.x;
    if (i < N_EDG) atomicAdd(&deg[e[3 * i + 2]], 1.0f);
}

// pack weights into fragment-major tf32 layout:
// out[((nt*25+ks)*64 + c)*8 + t*2+half] = tf32(W[ks*8+t+half*4][nt*64+c])
__global__ void packW1fm_kernel(const float* __restrict__ Wa, const float* __restrict__ Wb,
                                const float* __restrict__ Wc, float* __restrict__ out) {
    int idx = blockIdx.x * blockDim.x + threadIdx.x;
    if (idx >= NT1 * BTILE) return;
    int nt = idx / BTILE, rem = idx % BTILE;
    int ks = rem / 512, rem2 = rem % 512;
    int c = rem2 >> 3, e = rem2 & 7;
    int t = e >> 1, half = e & 1;
    int k = ks * 8 + t + half * 4;
    int n = nt * 64 + c;
    float v = 0.f;
    if (n < 200)      v = Wa[k * 200 + n];
    else if (n < 400) v = Wb[k * 200 + n - 200];
    else if (n < 600) v = Wc[k * 200 + n - 400];
    out[idx] = to_tf32(v);
}

__global__ void packW2fm_kernel(const float* __restrict__ Wa, const float* __restrict__ Wb,
                                float* __restrict__ out) {
    int idx = blockIdx.x * blockDim.x + threadIdx.x;
    if (idx >= NT2 * BTILE) return;
    int nt = idx / BTILE, rem = idx % BTILE;
    int ks = rem / 512, rem2 = rem % 512;
    int c = rem2 >> 3, e = rem2 & 7;
    int t = e >> 1, half = e & 1;
    int k = ks * 8 + t + half * 4;
    int n = nt * 64 + c;
    float v = 0.f;
    if (n < 200)      v = Wa[k * 200 + n];
    else if (n < 400) v = Wb[k * 200 + n - 200];
    out[idx] = to_tf32(v);
}

// warp-per-edge scatter; red.global (no return) vectorized
__global__ void scatter_kernel(const int* __restrict__ e,
                               const float* __restrict__ A, int astr,
                               const float* __restrict__ rA,
                               float* __restrict__ agg) {
    int warp = (blockIdx.x * blockDim.x + threadIdx.x) >> 5;
    int lane = threadIdx.x & 31;
    if (warp >= N_EDG) return;
    int src = e[3 * warp + 0];
    int rel = e[3 * warp + 1];
    int dst = e[3 * warp + 2];
    const float4* a  = (const float4*)(A  + (size_t)src * astr);
    const float4* ra = (const float4*)(rA + (size_t)rel * DIMV);
    float4*       d  = (float4*)(agg + (size_t)dst * DIMV);
    #pragma unroll 2
    for (int c = lane; c < DIMV / 4; c += 32) {
        float4 va = a[c], vr = ra[c];
        float4 v = make_float4(va.x + vr.x, va.y + vr.y, va.z + vr.z, va.w + vr.w);
        asm volatile("red.global.add.v4.f32 [%0], {%1,%2,%3,%4};"
                     :: "l"(d + c), "f"(v.x), "f"(v.y), "f"(v.z), "f"(v.w)
                     : "memory");
    }
}

// ---------------- tf32 MMA GEMM v3b: A in registers, B cp.async dbuf -------
// Out[M, NT*64] = A[M,200] @ Bfm (frag-major packed weights)
// AFILL 0: A = Asrc;  AFILL 1: A = Asrc + agg/max(deg,1)
// CTA = 128 threads / 4 warps; warp w owns rows [blk*64 + w*16, +16),
// and computes ALL 64 columns of each tile (ni = 0..7).
template <int AFILL>
__global__ void __launch_bounds__(128, 2)
mma_gemm(const float* __restrict__ Asrc, int astride,
         const float* __restrict__ agg, const float* __restrict__ deg,
         const float* __restrict__ Bfm,
         float* __restrict__ Out, int ostride, int realN,
         int M, int NT) {
    extern __shared__ float smf[];
    float* Bs = smf;             // 2 * BTILE floats
    const int tid  = threadIdx.x;
    const int wid  = tid >> 5, lane = tid & 31;
    const int gid  = lane >> 2, tig = lane & 3;
    const int row0 = blockIdx.x * BM;

    // ---- prefetch B tile 0 (issue first so A LDGs overlap it) ----
    {
        const float4* src = (const float4*)Bfm;
        float4* dst = (float4*)Bs;
        #pragma unroll 5
        for (int i = tid; i < BTILE / 4; i += 128) cpa16(dst + i, src + i);
        CP_COMMIT();
    }

    // ---- A fill: GMEM -> registers, fragment order ----
    uint32_t a[25][4];
    {
        int grow0 = row0 + wid * 16 + gid;
        int grow1 = grow0 + 8;
        int r0c = min(grow0, M - 1), r1c = min(grow1, M - 1);
        const float* ap0 = Asrc + (size_t)r0c * astride;
        const float* ap1 = Asrc + (size_t)r1c * astride;
        const float* gp0 = agg + (size_t)r0c * DIMV;
        const float* gp1 = agg + (size_t)r1c * DIMV;
        float invd0 = 1.f, invd1 = 1.f;
        if (AFILL == 1) {
            invd0 = 1.f / fmaxf(deg[r0c], 1.f);
            invd1 = 1.f / fmaxf(deg[r1c], 1.f);
        }
        #pragma unroll
        for (int ks = 0; ks < 25; ks++) {
            int k = ks * 8 + tig;
            float x0 = ap0[k],     x1 = ap1[k];
            float x2 = ap0[k + 4], x3 = ap1[k + 4];
            if (AFILL == 1) {
                x0 += gp0[k] * invd0;     x1 += gp1[k] * invd1;
                x2 += gp0[k + 4] * invd0; x3 += gp1[k + 4] * invd1;
            }
            a[ks][0] = __float_as_uint(to_tf32(x0));
            a[ks][1] = __float_as_uint(to_tf32(x1));
            a[ks][2] = __float_as_uint(to_tf32(x2));
            a[ks][3] = __float_as_uint(to_tf32(x3));
        }
    }

    for (int nt = 0; nt < NT; nt++) {
        CP_WAIT0();
        __syncthreads();
        if (nt + 1 < NT) {
            const float4* src = (const float4*)(Bfm + (size_t)(nt + 1) * BTILE);
            float4* dst = (float4*)(Bs + ((nt + 1) & 1) * BTILE);
            #pragma unroll 5
            for (int i = tid; i < BTILE / 4; i += 128) cpa16(dst + i, src + i);
            CP_COMMIT();
        }
        const float2* B2 = (const float2*)(Bs + (nt & 1) * BTILE);

        float acc[8][4];
        #pragma unroll
        for (int ni = 0; ni < 8; ni++)
            #pragma unroll
            for (int q = 0; q < 4; q++) acc[ni][q] = 0.f;

        #pragma unroll
        for (int ks = 0; ks < 25; ks++) {
            uint32_t b[8][2];
            #pragma unroll
            for (int ni = 0; ni < 8; ni++)
                *(float2*)b[ni] = B2[(ks * 64 + ni * 8 + gid) * 4 + tig];
            #pragma unroll
            for (int ni = 0; ni < 8; ni++)
                mma8(acc[ni], a[ks], b[ni]);
        }

        // ---- epilogue: masked strided stores (full 64 cols) ----
        int n0 = nt * 64;
        int grow = row0 + wid * 16 + gid;
        #pragma unroll
        for (int ni = 0; ni < 8; ni++) {
            int gcol = n0 + ni * 8 + tig * 2;
            if (gcol < realN) {
                if (grow < M)
                    *(float2*)(Out + (size_t)grow * ostride + gcol) =
                        make_float2(acc[ni][0], acc[ni][1]);
                if (grow + 8 < M)
                    *(float2*)(Out + (size_t)(grow + 8) * ostride + gcol) =
                        make_float2(acc[ni][2], acc[ni][3]);
            }
        }
        __syncthreads();
    }
}

// ------- fused final: gate=sig(Graw+b); c2=L2raw+agg2/deg; h'=l2n(g*l2n(c2)+(1-g)h)
__global__ void final_kernel(const float* __restrict__ P1,
                             const float* __restrict__ bias,
                             const float* __restrict__ P2,
                             const float* __restrict__ agg2,
                             const float* __restrict__ deg,
                             const float* __restrict__ hin,
                             float* __restrict__ hout) {
    int warp = (blockIdx.x * blockDim.x + threadIdx.x) >> 5;
    int lane = threadIdx.x & 31;
    if (warp >= N_NODES) return;
    const float* graw = P1 + (size_t)warp * NP1 + 400;
    const float* l2r  = P2 + (size_t)warp * NP2 + 200;
    const float* ag   = agg2 + (size_t)warp * DIMV;
    const float* hp   = hin + (size_t)warp * DIMV;
    float invd = 1.f / fmaxf(deg[warp], 1.f);

    float cv[7], gv[7], hv[7];
    float s = 0.f;
    #pragma unroll
    for (int i = 0; i < 7; i++) {
        int j = lane + i * 32;
        float x = 0.f, g = 0.f, hh = 0.f;
        if (j < DIMV) {
            x  = l2r[j] + ag[j] * invd;
            g  = 1.f / (1.f + expf(-(graw[j] + bias[j])));
            hh = hp[j];
        }
        cv[i] = x; gv[i] = g; hv[i] = hh;
        s += x * x;
    }
    #pragma unroll
    for (int o = 16; o; o >>= 1) s += __shfl_xor_sync(0xffffffffu, s, o);
    float inv = 1.f / fmaxf(sqrtf(s), 1e-12f);

    float s2 = 0.f;
    #pragma unroll
    for (int i = 0; i < 7; i++) {
        float v = gv[i] * (cv[i] * inv) + (1.f - gv[i]) * hv[i];
        cv[i] = v;
        s2 += v * v;
    }
    #pragma unroll
    for (int o = 16; o; o >>= 1) s2 += __shfl_xor_sync(0xffffffffu, s2, o);
    float inv2 = 1.f / fmaxf(sqrtf(s2), 1e-12f);

    float* op = hout + (size_t)warp * DIMV;
    #pragma unroll
    for (int i = 0; i < 7; i++) {
        int j = lane + i * 32;
        if (j < DIMV) op[j] = cv[i] * inv2;
    }
}

// ---------------- host launcher --------------------------------------------
extern "C" void kernel_launch(void* const* d_in, const int* in_sizes, int n_in,
                              void* d_out, int out_size) {
    const int*   edges = (const int*)d_in[0];
    const float* ent   = (const float*)d_in[1];
    const float* rele  = (const float*)d_in[2];
    const float* Wm1   = (const float*)d_in[3];
    const float* Wl1   = (const float*)d_in[4];
    const float* Wm2   = (const float*)d_in[5];
    const float* Wl2   = (const float*)d_in[6];
    const float* Wg    = (const float*)d_in[7];
    const float* bg    = (const float*)d_in[8];
    float* out = (float*)d_out;

    float *h, *r, *P1, *P2, *agg1, *agg2, *rA1, *rA2, *W1fm, *W2fm, *deg;
    cudaGetSymbolAddress((void**)&h,    g_h);
    cudaGetSymbolAddress((void**)&r,    g_r);
    cudaGetSymbolAddress((void**)&P1,   g_P1);
    cudaGetSymbolAddress((void**)&P2,   g_P2);
    cudaGetSymbolAddress((void**)&agg1, g_agg1);
    cudaGetSymbolAddress((void**)&agg2, g_agg2);
    cudaGetSymbolAddress((void**)&rA1,  g_rA1);
    cudaGetSymbolAddress((void**)&rA2,  g_rA2);
    cudaGetSymbolAddress((void**)&W1fm, g_W1fm);
    cudaGetSymbolAddress((void**)&W2fm, g_W2fm);
    cudaGetSymbolAddress((void**)&deg,  g_deg);

    cudaFuncSetAttribute(mma_gemm<0>, cudaFuncAttributeMaxDynamicSharedMemorySize, SMEMB);
    cudaFuncSetAttribute(mma_gemm<1>, cudaFuncAttributeMaxDynamicSharedMemorySize, SMEMB);

    const int grid_m  = (N_NODES + BM - 1) / BM;  // 1563
    const int grid_mr = (N_RELS + BM - 1) / BM;   // 8
    const int n_agg4  = (N_NODES * DIMV) / 4;
    const int n_deg4  = N_NODES / 4;

    // Launch order chosen so ncu (-s 5 -c 1) profiles the BIG GEMM1 (launch #5).
    l2norm_kernel<<<(N_NODES + 7) / 8, 256>>>(ent, h, N_NODES);                 // 0
    l2norm_kernel<<<(N_RELS + 7) / 8, 256>>>(rele, r, N_RELS);                  // 1
    packW1fm_kernel<<<(NT1 * BTILE + 255) / 256, 256>>>(Wm1, Wl1, Wg, W1fm);    // 2
    packW2fm_kernel<<<(NT2 * BTILE + 255) / 256, 256>>>(Wm2, Wl2, W2fm);        // 3
    zero4_kernel<<<(n_deg4 + 255) / 256, 256>>>((float4*)deg, n_deg4);          // 4
    // 5: BIG GEMM1 of t=0 (profiled by ncu)
    mma_gemm<0><<<grid_m, 128, SMEMB>>>(h, DIMV, nullptr, nullptr, W1fm,
                                        P1, NP1, 600, N_NODES, NT1);
    // time-invariant relation GEMMs
    mma_gemm<0><<<grid_mr, 128, SMEMB>>>(r, DIMV, nullptr, nullptr, W1fm,
                                         rA1, DIMV, DIMV, N_RELS, 4);
    mma_gemm<0><<<grid_mr, 128, SMEMB>>>(r, DIMV, nullptr, nullptr, W2fm,
                                         rA2, DIMV, DIMV, N_RELS, 4);

    for (int t = 0; t < 3; t++) {
        const int* e = edges + (size_t)t * N_EDG * 3;

        if (t > 0) {
            zero4_kernel<<<(n_deg4 + 255) / 256, 256>>>((float4*)deg, n_deg4);
            // P1 = h @ [Wm1 | Wl1 | Wg]
            mma_gemm<0><<<grid_m, 128, SMEMB>>>(h, DIMV, nullptr, nullptr, W1fm,
                                                P1, NP1, 600, N_NODES, NT1);
        }
        deg_kernel<<<(N_EDG + 255) / 256, 256>>>(e, deg);
        zero4_kernel<<<(n_agg4 + 255) / 256, 256>>>((float4*)agg1, n_agg4);
        scatter_kernel<<<(N_EDG + 7) / 8, 256>>>(e, P1, NP1, rA1, agg1);

        zero4_kernel<<<(n_agg4 + 255) / 256, 256>>>((float4*)agg2, n_agg4);
        // P2 = c1 @ [Wm2 | Wl2], c1 = L1 + agg1/deg computed in A-fill
        mma_gemm<1><<<grid_m, 128, SMEMB>>>(P1 + 200, NP1, agg1, deg, W2fm,
                                            P2, NP2, 400, N_NODES, NT2);
        scatter_kernel<<<(N_EDG + 7) / 8, 256>>>(e, P2, NP2, rA2, agg2);

        final_kernel<<<(N_NODES + 7) / 8, 256>>>(P1, bg, P2, agg2, deg, h,
                                                 (t == 2) ? out : h);
    }
}

// round 12
// speedup vs baseline: 1.8670x; 1.3535x over previous
#include <cuda_runtime.h>
#include <cuda_fp16.h>
#include <math.h>
#include <stdint.h>

#define N_NODES 100000
#define N_RELS  500
#define DIMV    200
#define N_EDG   200000
#define NP1     640   // P1 row stride: [A1 | L1 | Graw | pad]
#define NP2     448   // P2 row stride: [A2 | L2 | pad]
#define BM      64
#define NT1     10    // 640/64 tiles
#define NT2     7     // 448/64 tiles
#define KS16    13    // K=200 -> 13 k-steps of 16 (padded to 208)
#define TILE_U32 (KS16 * 64 * 8)      // 6656 u32 per packed fp16 B tile (26624 B)
#define SMEMB   (2 * TILE_U32 * 4)    // 53248 B double buffer

// ---------------- scratch (device globals; no allocation allowed) ----------
__device__ float g_h  [(size_t)N_NODES * DIMV];
__device__ float g_r  [(size_t)N_RELS  * DIMV];
__device__ float g_P1 [(size_t)N_NODES * NP1];
__device__ float g_P2 [(size_t)N_NODES * NP2];
__device__ float g_agg1[(size_t)N_NODES * DIMV];
__device__ float g_agg2[(size_t)N_NODES * DIMV];
__device__ float g_rA1[(size_t)N_RELS * DIMV];
__device__ float g_rA2[(size_t)N_RELS * DIMV];
__device__ uint32_t g_B1h[(size_t)NT1 * TILE_U32];  // frag-major fp16 [Wm1|Wl1|Wg]
__device__ uint32_t g_B2h[(size_t)NT2 * TILE_U32];  // frag-major fp16 [Wm2|Wl2]
__device__ float g_deg[N_NODES];

// ---------------- helpers ---------------------------------------------------
__device__ __forceinline__ void mma16(float* c, const uint32_t* a, const uint32_t* b) {
    asm volatile(
        "mma.sync.aligned.m16n8k16.row.col.f32.f16.f16.f32 "
        "{%0,%1,%2,%3},{%4,%5,%6,%7},{%8,%9},{%0,%1,%2,%3};"
        : "+f"(c[0]), "+f"(c[1]), "+f"(c[2]), "+f"(c[3])
        : "r"(a[0]), "r"(a[1]), "r"(a[2]), "r"(a[3]), "r"(b[0]), "r"(b[1]));
}

__device__ __forceinline__ uint32_t f2h2(float x, float y) {
    __half2 t = __floats2half2_rn(x, y);   // low = x (lower k index), high = y
    return *(uint32_t*)&t;
}

__device__ __forceinline__ void cpa16(void* sdst, const void* gsrc) {
    uint32_t s = (uint32_t)__cvta_generic_to_shared(sdst);
    asm volatile("cp.async.cg.shared.global [%0], [%1], 16;" :: "r"(s), "l"(gsrc));
}
#define CP_COMMIT() asm volatile("cp.async.commit_group;")
#define CP_WAIT0()  asm volatile("cp.async.wait_group 0;")

// ---------------- small utility kernels ------------------------------------
__global__ void zero_step_kernel(float4* __restrict__ a1, float4* __restrict__ a2,
                                 float4* __restrict__ dg) {
    int i = blockIdx.x * blockDim.x + threadIdx.x;
    const float4 z = make_float4(0.f, 0.f, 0.f, 0.f);
    if (i < (N_NODES * DIMV) / 4) { a1[i] = z; a2[i] = z; }
    if (i < N_NODES / 4) dg[i] = z;
}

__global__ void l2norm_kernel(const float* __restrict__ in, float* __restrict__ out, int rows) {
    int warp = (blockIdx.x * blockDim.x + threadIdx.x) >> 5;
    int lane = threadIdx.x & 31;
    if (warp >= rows) return;
    const float* p = in + (size_t)warp * DIMV;
    float s = 0.f;
    #pragma unroll
    for (int i = 0; i < 7; i++) {
        int j = lane + i * 32;
        float v = (j < DIMV) ? p[j] : 0.f;
        s += v * v;
    }
    #pragma unroll
    for (int o = 16; o; o >>= 1) s += __shfl_xor_sync(0xffffffffu, s, o);
    float inv = 1.f / fmaxf(sqrtf(s), 1e-12f);
    float* q = out + (size_t)warp * DIMV;
    #pragma unroll
    for (int i = 0; i < 7; i++) {
        int j = lane + i * 32;
        if (j < DIMV) q[j] = p[j] * inv;
    }
}

// pack weights -> fragment-major fp16.
// u32 slot layout per (nt, ks, c): 8 slots, e = tig*2 + hi;
// slot holds k indices k0 = ks*16 + 2*tig + hi*8 (low) and k0+1 (high), col n = nt*64+c.
__global__ void packB1h_kernel(const float* __restrict__ Wa, const float* __restrict__ Wb,
                               const float* __restrict__ Wc, uint32_t* __restrict__ out) {
    int idx = blockIdx.x * blockDim.x + threadIdx.x;
    if (idx >= NT1 * TILE_U32) return;
    int nt = idx / TILE_U32, rem = idx % TILE_U32;
    int ks = rem / 512;
    int c  = (rem >> 3) & 63;
    int e  = rem & 7;
    int k0 = ks * 16 + (e >> 1) * 2 + (e & 1) * 8;
    int n  = nt * 64 + c;
    float v0 = 0.f, v1 = 0.f;
    if (n < 600) {
        const float* W = (n < 200) ? Wa : (n < 400) ? Wb : Wc;
        int nn = (n < 200) ? n : (n < 400) ? n - 200 : n - 400;
        if (k0 < 200)     v0 = W[k0 * 200 + nn];
        if (k0 + 1 < 200) v1 = W[(k0 + 1) * 200 + nn];
    }
    out[idx] = f2h2(v0, v1);
}

__global__ void packB2h_kernel(const float* __restrict__ Wa, const float* __restrict__ Wb,
                               uint32_t* __restrict__ out) {
    int idx = blockIdx.x * blockDim.x + threadIdx.x;
    if (idx >= NT2 * TILE_U32) return;
    int nt = idx / TILE_U32, rem = idx % TILE_U32;
    int ks = rem / 512;
    int c  = (rem >> 3) & 63;
    int e  = rem & 7;
    int k0 = ks * 16 + (e >> 1) * 2 + (e & 1) * 8;
    int n  = nt * 64 + c;
    float v0 = 0.f, v1 = 0.f;
    if (n < 400) {
        const float* W = (n < 200) ? Wa : Wb;
        int nn = (n < 200) ? n : n - 200;
        if (k0 < 200)     v0 = W[k0 * 200 + nn];
        if (k0 + 1 < 200) v1 = W[(k0 + 1) * 200 + nn];
    }
    out[idx] = f2h2(v0, v1);
}

// warp-per-edge scatter; optional fused degree count; red.global vectorized
__global__ void scatter_kernel(const int* __restrict__ e,
                               const float* __restrict__ A, int astr,
                               const float* __restrict__ rA,
                               float* __restrict__ agg, float* __restrict__ degp) {
    int warp = (blockIdx.x * blockDim.x + threadIdx.x) >> 5;
    int lane = threadIdx.x & 31;
    if (warp >= N_EDG) return;
    int src = e[3 * warp + 0];
    int rel = e[3 * warp + 1];
    int dst = e[3 * warp + 2];
    if (degp && lane == 0)
        asm volatile("red.global.add.f32 [%0], %1;" :: "l"(degp + dst), "f"(1.0f) : "memory");
    const float4* a  = (const float4*)(A  + (size_t)src * astr);
    const float4* ra = (const float4*)(rA + (size_t)rel * DIMV);
    float4*       d  = (float4*)(agg + (size_t)dst * DIMV);
    #pragma unroll 2
    for (int c = lane; c < DIMV / 4; c += 32) {
        float4 va = a[c], vr = ra[c];
        float4 v = make_float4(va.x + vr.x, va.y + vr.y, va.z + vr.z, va.w + vr.w);
        asm volatile("red.global.add.v4.f32 [%0], {%1,%2,%3,%4};"
                     :: "l"(d + c), "f"(v.x), "f"(v.y), "f"(v.z), "f"(v.w)
                     : "memory");
    }
}

// ---------------- fp16 MMA GEMM: A in registers, B cp.async dbuf -----------
// Out[M, NT*64] = A[M,200] @ Bh (frag-major packed fp16 weights)
// AFILL 0: A = Asrc;  AFILL 1: A = Asrc + agg/max(deg,1)
// CTA = 128 threads / 4 warps; warp w owns rows [blk*64 + w*16, +16),
// computes all 64 columns of each tile.
template <int AFILL>
__global__ void __launch_bounds__(128, 3)
mma_gemm(const float* __restrict__ Asrc, int astride,
         const float* __restrict__ agg, const float* __restrict__ deg,
         const uint32_t* __restrict__ Bh,
         float* __restrict__ Out, int ostride, int realN,
         int M, int NT) {
    extern __shared__ uint32_t smu[];
    const int tid  = threadIdx.x;
    const int wid  = tid >> 5, lane = tid & 31;
    const int gid  = lane >> 2, tig = lane & 3;
    const int row0 = blockIdx.x * BM;

    // ---- prefetch B tile 0 (issue first so A LDGs overlap it) ----
    {
        const uint4* src = (const uint4*)Bh;
        uint4* dst = (uint4*)smu;
        #pragma unroll 13
        for (int i = tid; i < TILE_U32 / 4; i += 128) cpa16(dst + i, src + i);
        CP_COMMIT();
    }

    // ---- A fill: GMEM -> fp16 registers, fragment order ----
    uint32_t a[KS16][4];
    {
        int grow0 = row0 + wid * 16 + gid;
        int grow1 = grow0 + 8;
        int r0c = min(grow0, M - 1), r1c = min(grow1, M - 1);
        const float* ap0 = Asrc + (size_t)r0c * astride;
        const float* ap1 = Asrc + (size_t)r1c * astride;
        const float* gp0 = agg + (size_t)r0c * DIMV;
        const float* gp1 = agg + (size_t)r1c * DIMV;
        float invd0 = 1.f, invd1 = 1.f;
        if (AFILL == 1) {
            invd0 = 1.f / fmaxf(deg[r0c], 1.f);
            invd1 = 1.f / fmaxf(deg[r1c], 1.f);
        }
        #pragma unroll
        for (int ks = 0; ks < KS16; ks++) {
            int k1 = ks * 16 + 2 * tig;   // always < 200
            int k2 = k1 + 8;
            float2 x00 = *(const float2*)(ap0 + k1);
            float2 x10 = *(const float2*)(ap1 + k1);
            float2 x01 = make_float2(0.f, 0.f), x11 = make_float2(0.f, 0.f);
            if (k2 < 200) {
                x01 = *(const float2*)(ap0 + k2);
                x11 = *(const float2*)(ap1 + k2);
            }
            if (AFILL == 1) {
                float2 g00 = *(const float2*)(gp0 + k1);
                float2 g10 = *(const float2*)(gp1 + k1);
                x00.x += g00.x * invd0; x00.y += g00.y * invd0;
                x10.x += g10.x * invd1; x10.y += g10.y * invd1;
                if (k2 < 200) {
                    float2 g01 = *(const float2*)(gp0 + k2);
                    float2 g11 = *(const float2*)(gp1 + k2);
                    x01.x += g01.x * invd0; x01.y += g01.y * invd0;
                    x11.x += g11.x * invd1; x11.y += g11.y * invd1;
                }
            }
            a[ks][0] = f2h2(x00.x, x00.y);
            a[ks][1] = f2h2(x10.x, x10.y);
            a[ks][2] = f2h2(x01.x, x01.y);
            a[ks][3] = f2h2(x11.x, x11.y);
        }
    }

    for (int nt = 0; nt < NT; nt++) {
        CP_WAIT0();
        __syncthreads();
        if (nt + 1 < NT) {
            const uint4* src = (const uint4*)(Bh + (size_t)(nt + 1) * TILE_U32);
            uint4* dst = (uint4*)(smu + ((nt + 1) & 1) * TILE_U32);
            #pragma unroll 13
            for (int i = tid; i < TILE_U32 / 4; i += 128) cpa16(dst + i, src + i);
            CP_COMMIT();
        }
        const uint2* B2 = (const uint2*)(smu + (nt & 1) * TILE_U32);

        float acc[8][4];
        #pragma unroll
        for (int ni = 0; ni < 8; ni++)
            #pragma unroll
            for (int q = 0; q < 4; q++) acc[ni][q] = 0.f;

        #pragma unroll
        for (int ks = 0; ks < KS16; ks++) {
            uint32_t b[8][2];
            #pragma unroll
            for (int ni = 0; ni < 8; ni++)
                *(uint2*)b[ni] = B2[(ks * 64 + ni * 8 + gid) * 4 + tig];
            #pragma unroll
            for (int ni = 0; ni < 8; ni++)
                mma16(acc[ni], a[ks], b[ni]);
        }

        // ---- epilogue: masked strided stores (full 64 cols) ----
        int n0 = nt * 64;
        int grow = row0 + wid * 16 + gid;
        #pragma unroll
        for (int ni = 0; ni < 8; ni++) {
            int gcol = n0 + ni * 8 + tig * 2;
            if (gcol < realN) {
                if (grow < M)
                    *(float2*)(Out + (size_t)grow * ostride + gcol) =
                        make_float2(acc[ni][0], acc[ni][1]);
                if (grow + 8 < M)
                    *(float2*)(Out + (size_t)(grow + 8) * ostride + gcol) =
                        make_float2(acc[ni][2], acc[ni][3]);
            }
        }
        __syncthreads();
    }
}

// ------- fused final: gate=sig(Graw+b); c2=L2raw+agg2/deg; h'=l2n(g*l2n(c2)+(1-g)h)
__global__ void final_kernel(const float* __restrict__ P1,
                             const float* __restrict__ bias,
                             const float* __restrict__ P2,
                             const float* __restrict__ agg2,
                             const float* __restrict__ deg,
                             const float* __restrict__ hin,
                             float* __restrict__ hout) {
    int warp = (blockIdx.x * blockDim.x + threadIdx.x) >> 5;
    int lane = threadIdx.x & 31;
    if (warp >= N_NODES) return;
    const float* graw = P1 + (size_t)warp * NP1 + 400;
    const float* l2r  = P2 + (size_t)warp * NP2 + 200;
    const float* ag   = agg2 + (size_t)warp * DIMV;
    const float* hp   = hin + (size_t)warp * DIMV;
    float invd = 1.f / fmaxf(deg[warp], 1.f);

    float cv[7], gv[7], hv[7];
    float s = 0.f;
    #pragma unroll
    for (int i = 0; i < 7; i++) {
        int j = lane + i * 32;
        float x = 0.f, g = 0.f, hh = 0.f;
        if (j < DIMV) {
            x  = l2r[j] + ag[j] * invd;
            g  = 1.f / (1.f + expf(-(graw[j] + bias[j])));
            hh = hp[j];
        }
        cv[i] = x; gv[i] = g; hv[i] = hh;
        s += x * x;
    }
    #pragma unroll
    for (int o = 16; o; o >>= 1) s += __shfl_xor_sync(0xffffffffu, s, o);
    float inv = 1.f / fmaxf(sqrtf(s), 1e-12f);

    float s2 = 0.f;
    #pragma unroll
    for (int i = 0; i < 7; i++) {
        float v = gv[i] * (cv[i] * inv) + (1.f - gv[i]) * hv[i];
        cv[i] = v;
        s2 += v * v;
    }
    #pragma unroll
    for (int o = 16; o; o >>= 1) s2 += __shfl_xor_sync(0xffffffffu, s2, o);
    float inv2 = 1.f / fmaxf(sqrtf(s2), 1e-12f);

    float* op = hout + (size_t)warp * DIMV;
    #pragma unroll
    for (int i = 0; i < 7; i++) {
        int j = lane + i * 32;
        if (j < DIMV) op[j] = cv[i] * inv2;
    }
}

// ---------------- host launcher --------------------------------------------
extern "C" void kernel_launch(void* const* d_in, const int* in_sizes, int n_in,
                              void* d_out, int out_size) {
    const int*   edges = (const int*)d_in[0];
    const float* ent   = (const float*)d_in[1];
    const float* rele  = (const float*)d_in[2];
    const float* Wm1   = (const float*)d_in[3];
    const float* Wl1   = (const float*)d_in[4];
    const float* Wm2   = (const float*)d_in[5];
    const float* Wl2   = (const float*)d_in[6];
    const float* Wg    = (const float*)d_in[7];
    const float* bg    = (const float*)d_in[8];
    float* out = (float*)d_out;

    float *h, *r, *P1, *P2, *agg1, *agg2, *rA1, *rA2, *deg;
    uint32_t *B1h, *B2h;
    cudaGetSymbolAddress((void**)&h,    g_h);
    cudaGetSymbolAddress((void**)&r,    g_r);
    cudaGetSymbolAddress((void**)&P1,   g_P1);
    cudaGetSymbolAddress((void**)&P2,   g_P2);
    cudaGetSymbolAddress((void**)&agg1, g_agg1);
    cudaGetSymbolAddress((void**)&agg2, g_agg2);
    cudaGetSymbolAddress((void**)&rA1,  g_rA1);
    cudaGetSymbolAddress((void**)&rA2,  g_rA2);
    cudaGetSymbolAddress((void**)&B1h,  g_B1h);
    cudaGetSymbolAddress((void**)&B2h,  g_B2h);
    cudaGetSymbolAddress((void**)&deg,  g_deg);

    cudaFuncSetAttribute(mma_gemm<0>, cudaFuncAttributeMaxDynamicSharedMemorySize, SMEMB);
    cudaFuncSetAttribute(mma_gemm<1>, cudaFuncAttributeMaxDynamicSharedMemorySize, SMEMB);

    const int grid_m  = (N_NODES + BM - 1) / BM;  // 1563
    const int grid_mr = (N_RELS + BM - 1) / BM;   // 8
    const int grid_z  = ((N_NODES * DIMV) / 4 + 255) / 256;

    // Launch order: big GEMM1 is launch index 3 (the one ncu profiles).
    l2norm_kernel<<<(N_NODES + 7) / 8, 256>>>(ent, h, N_NODES);                   // 0
    l2norm_kernel<<<(N_RELS + 7) / 8, 256>>>(rele, r, N_RELS);                    // 1
    packB1h_kernel<<<(NT1 * TILE_U32 + 255) / 256, 256>>>(Wm1, Wl1, Wg, B1h);     // 2
    // 3: BIG GEMM1 of t=0 (profiled)
    mma_gemm<0><<<grid_m, 128, SMEMB>>>(h, DIMV, nullptr, nullptr, B1h,
                                        P1, NP1, 600, N_NODES, NT1);
    packB2h_kernel<<<(NT2 * TILE_U32 + 255) / 256, 256>>>(Wm2, Wl2, B2h);         // 4
    // time-invariant relation projections (first 200 packed cols)
    mma_gemm<0><<<grid_mr, 128, SMEMB>>>(r, DIMV, nullptr, nullptr, B1h,
                                         rA1, DIMV, 200, N_RELS, 4);
    mma_gemm<0><<<grid_mr, 128, SMEMB>>>(r, DIMV, nullptr, nullptr, B2h,
                                         rA2, DIMV, 200, N_RELS, 4);

    for (int t = 0; t < 3; t++) {
        const int* e = edges + (size_t)t * N_EDG * 3;

        if (t > 0)
            mma_gemm<0><<<grid_m, 128, SMEMB>>>(h, DIMV, nullptr, nullptr, B1h,
                                                P1, NP1, 600, N_NODES, NT1);
        zero_step_kernel<<<grid_z, 256>>>((float4*)agg1, (float4*)agg2, (float4*)deg);
        scatter_kernel<<<(N_EDG + 7) / 8, 256>>>(e, P1, NP1, rA1, agg1, deg);

        mma_gemm<1><<<grid_m, 128, SMEMB>>>(P1 + 200, NP1, agg1, deg, B2h,
                                            P2, NP2, 400, N_NODES, NT2);
        scatter_kernel<<<(N_EDG + 7) / 8, 256>>>(e, P2, NP2, rA2, agg2, nullptr);

        final_kernel<<<(N_NODES + 7) / 8, 256>>>(P1, bg, P2, agg2, deg, h,
                                                 (t == 2) ? out : h);
    }
}

// round 15
// speedup vs baseline: 1.8843x; 1.0093x over previous
#include <cuda_runtime.h>
#include <cuda_fp16.h>
#include <math.h>
#include <stdint.h>

#define N_NODES 100000
#define N_RELS  500
#define DIMV    200
#define N_EDG   200000
#define NP1     640   // P1 row stride: [A1 | L1 | Graw | pad]
#define NP2     448   // P2 row stride: [A2 | L2 | pad]
#define BM      64
#define NT1     10    // 640/64 tiles
#define NT2     7     // 448/64 tiles
#define KS16    13    // K=200 -> 13 k-steps of 16 (padded to 208)
#define TILE_U32 (KS16 * 64 * 8)      // 6656 u32 per packed fp16 B tile (26624 B)
#define SMEMB   (2 * TILE_U32 * 4)    // 53248 B double buffer

// ---------------- scratch (device globals; no allocation allowed) ----------
__device__ float g_h  [(size_t)N_NODES * DIMV];
__device__ float g_r  [(size_t)N_RELS  * DIMV];
__device__ float g_P1 [(size_t)N_NODES * NP1];
__device__ float g_P2 [(size_t)N_NODES * NP2];
__device__ float g_agg1[(size_t)N_NODES * DIMV];
__device__ float g_agg2[(size_t)N_NODES * DIMV];
__device__ float g_rA1[(size_t)N_RELS * DIMV];
__device__ float g_rA2[(size_t)N_RELS * DIMV];
__device__ uint32_t g_B1h[(size_t)NT1 * TILE_U32];  // frag-major fp16 [Wm1|Wl1|Wg]
__device__ uint32_t g_B2h[(size_t)NT2 * TILE_U32];  // frag-major fp16 [Wm2|Wl2]
__device__ float g_deg[N_NODES];

// ---------------- helpers ---------------------------------------------------
__device__ __forceinline__ void mma16(float* c, const uint32_t* a, const uint32_t* b) {
    asm volatile(
        "mma.sync.aligned.m16n8k16.row.col.f32.f16.f16.f32 "
        "{%0,%1,%2,%3},{%4,%5,%6,%7},{%8,%9},{%0,%1,%2,%3};"
        : "+f"(c[0]), "+f"(c[1]), "+f"(c[2]), "+f"(c[3])
        : "r"(a[0]), "r"(a[1]), "r"(a[2]), "r"(a[3]), "r"(b[0]), "r"(b[1]));
}

__device__ __forceinline__ uint32_t f2h2(float x, float y) {
    __half2 t = __floats2half2_rn(x, y);   // low = x (lower k index), high = y
    return *(uint32_t*)&t;
}

__device__ __forceinline__ void cpa16(void* sdst, const void* gsrc) {
    uint32_t s = (uint32_t)__cvta_generic_to_shared(sdst);
    asm volatile("cp.async.cg.shared.global [%0], [%1], 16;" :: "r"(s), "l"(gsrc));
}
#define CP_COMMIT() asm volatile("cp.async.commit_group;")
#define CP_WAIT0()  asm volatile("cp.async.wait_group 0;")

// ---------------- small utility kernels ------------------------------------
__global__ void l2norm_kernel(const float* __restrict__ in, float* __restrict__ out, int rows) {
    int warp = (blockIdx.x * blockDim.x + threadIdx.x) >> 5;
    int lane = threadIdx.x & 31;
    if (warp >= rows) return;
    const float* p = in + (size_t)warp * DIMV;
    float s = 0.f;
    #pragma unroll
    for (int i = 0; i < 7; i++) {
        int j = lane + i * 32;
        float v = (j < DIMV) ? p[j] : 0.f;
        s += v * v;
    }
    #pragma unroll
    for (int o = 16; o; o >>= 1) s += __shfl_xor_sync(0xffffffffu, s, o);
    float inv = 1.f / fmaxf(sqrtf(s), 1e-12f);
    float* q = out + (size_t)warp * DIMV;
    #pragma unroll
    for (int i = 0; i < 7; i++) {
        int j = lane + i * 32;
        if (j < DIMV) q[j] = p[j] * inv;
    }
}

// pack weights -> fragment-major fp16.
// u32 slot layout per (nt, ks, c): 8 slots, e = tig*2 + hi;
// slot holds k indices k0 = ks*16 + 2*tig + hi*8 (low) and k0+1 (high), col n = nt*64+c.
__global__ void packB1h_kernel(const float* __restrict__ Wa, const float* __restrict__ Wb,
                               const float* __restrict__ Wc, uint32_t* __restrict__ out) {
    int idx = blockIdx.x * blockDim.x + threadIdx.x;
    if (idx >= NT1 * TILE_U32) return;
    int nt = idx / TILE_U32, rem = idx % TILE_U32;
    int ks = rem / 512;
    int c  = (rem >> 3) & 63;
    int e  = rem & 7;
    int k0 = ks * 16 + (e >> 1) * 2 + (e & 1) * 8;
    int n  = nt * 64 + c;
    float v0 = 0.f, v1 = 0.f;
    if (n < 600) {
        const float* W = (n < 200) ? Wa : (n < 400) ? Wb : Wc;
        int nn = (n < 200) ? n : (n < 400) ? n - 200 : n - 400;
        if (k0 < 200)     v0 = W[k0 * 200 + nn];
        if (k0 + 1 < 200) v1 = W[(k0 + 1) * 200 + nn];
    }
    out[idx] = f2h2(v0, v1);
}

__global__ void packB2h_kernel(const float* __restrict__ Wa, const float* __restrict__ Wb,
                               uint32_t* __restrict__ out) {
    int idx = blockIdx.x * blockDim.x + threadIdx.x;
    if (idx >= NT2 * TILE_U32) return;
    int nt = idx / TILE_U32, rem = idx % TILE_U32;
    int ks = rem / 512;
    int c  = (rem >> 3) & 63;
    int e  = rem & 7;
    int k0 = ks * 16 + (e >> 1) * 2 + (e & 1) * 8;
    int n  = nt * 64 + c;
    float v0 = 0.f, v1 = 0.f;
    if (n < 400) {
        const float* W = (n < 200) ? Wa : Wb;
        int nn = (n < 200) ? n : n - 200;
        if (k0 < 200)     v0 = W[k0 * 200 + nn];
        if (k0 + 1 < 200) v1 = W[(k0 + 1) * 200 + nn];
    }
    out[idx] = f2h2(v0, v1);
}

// warp-per-edge scatter; optional fused degree count; red.global vectorized
__global__ void scatter_kernel(const int* __restrict__ e,
                               const float* __restrict__ A, int astr,
                               const float* __restrict__ rA,
                               float* __restrict__ agg, float* __restrict__ degp) {
    int warp = (blockIdx.x * blockDim.x + threadIdx.x) >> 5;
    int lane = threadIdx.x & 31;
    if (warp >= N_EDG) return;
    int src = e[3 * warp + 0];
    int rel = e[3 * warp + 1];
    int dst = e[3 * warp + 2];
    if (degp && lane == 0)
        asm volatile("red.global.add.f32 [%0], %1;" :: "l"(degp + dst), "f"(1.0f) : "memory");
    const float4* a  = (const float4*)(A  + (size_t)src * astr);
    const float4* ra = (const float4*)(rA + (size_t)rel * DIMV);
    float4*       d  = (float4*)(agg + (size_t)dst * DIMV);
    #pragma unroll 2
    for (int c = lane; c < DIMV / 4; c += 32) {
        float4 va = a[c], vr = ra[c];
        float4 v = make_float4(va.x + vr.x, va.y + vr.y, va.z + vr.z, va.w + vr.w);
        asm volatile("red.global.add.v4.f32 [%0], {%1,%2,%3,%4};"
                     :: "l"(d + c), "f"(v.x), "f"(v.y), "f"(v.z), "f"(v.w)
                     : "memory");
    }
}

// ---------------- fp16 MMA GEMM (R12-proven BM=64 config) ------------------
// Out[M, NT*64] = A[M,200] @ Bh (frag-major packed fp16 weights)
// AFILL 0: A = Asrc;  AFILL 1: A = Asrc + agg/max(deg,1)
// ZERO 1: additionally zero z1/z2 rows [row0,row0+BM) (200 floats each) and
//         zdeg entries — replaces the standalone zero_step kernel.
// CTA = 128 threads / 4 warps; warp w owns rows [blk*64 + w*16, +16).
template <int AFILL, int ZERO>
__global__ void __launch_bounds__(128, 3)
mma_gemm(const float* __restrict__ Asrc, int astride,
         const float* __restrict__ agg, const float* __restrict__ deg,
         const uint32_t* __restrict__ Bh,
         float* __restrict__ Out, int ostride, int realN,
         int M, int NT,
         float* __restrict__ z1, float* __restrict__ z2,
         float* __restrict__ zdeg) {
    extern __shared__ uint32_t smu[];
    const int tid  = threadIdx.x;
    const int wid  = tid >> 5, lane = tid & 31;
    const int gid  = lane >> 2, tig = lane & 3;
    const int row0 = blockIdx.x * BM;

    // ---- prefetch B tile 0 (issue first so A LDGs overlap it) ----
    {
        const uint4* src = (const uint4*)Bh;
        uint4* dst = (uint4*)smu;
        #pragma unroll 13
        for (int i = tid; i < TILE_U32 / 4; i += 128) cpa16(dst + i, src + i);
        CP_COMMIT();
    }

    // ---- fused zeroing of agg1/agg2/deg rows for this block ----
    if (ZERO) {
        const float4 zz = make_float4(0.f, 0.f, 0.f, 0.f);
        int nrows = min(BM, M - row0);
        int n4 = nrows * (DIMV / 4);          // <= 3200
        float4* p1 = (float4*)(z1 + (size_t)row0 * DIMV);
        float4* p2 = (float4*)(z2 + (size_t)row0 * DIMV);
        for (int i = tid; i < n4; i += 128) { p1[i] = zz; p2[i] = zz; }
        if (tid < nrows) zdeg[row0 + tid] = 0.f;
    }

    // ---- A fill: GMEM -> fp16 registers, fragment order ----
    uint32_t a[KS16][4];
    {
        int grow0 = row0 + wid * 16 + gid;
        int grow1 = grow0 + 8;
        int r0c = min(grow0, M - 1), r1c = min(grow1, M - 1);
        const float* ap0 = Asrc + (size_t)r0c * astride;
        const float* ap1 = Asrc + (size_t)r1c * astride;
        const float* gp0 = agg + (size_t)r0c * DIMV;
        const float* gp1 = agg + (size_t)r1c * DIMV;
        float invd0 = 1.f, invd1 = 1.f;
        if (AFILL == 1) {
            invd0 = 1.f / fmaxf(deg[r0c], 1.f);
            invd1 = 1.f / fmaxf(deg[r1c], 1.f);
        }
        #pragma unroll
        for (int ks = 0; ks < KS16; ks++) {
            int k1 = ks * 16 + 2 * tig;   // always < 200
            int k2 = k1 + 8;
            float2 x00 = *(const float2*)(ap0 + k1);
            float2 x10 = *(const float2*)(ap1 + k1);
            float2 x01 = make_float2(0.f, 0.f), x11 = make_float2(0.f, 0.f);
            if (k2 < 200) {
                x01 = *(const float2*)(ap0 + k2);
                x11 = *(const float2*)(ap1 + k2);
            }
            if (AFILL == 1) {
                float2 g00 = *(const float2*)(gp0 + k1);
                float2 g10 = *(const float2*)(gp1 + k1);
                x00.x += g00.x * invd0; x00.y += g00.y * invd0;
                x10.x += g10.x * invd1; x10.y += g10.y * invd1;
                if (k2 < 200) {
                    float2 g01 = *(const float2*)(gp0 + k2);
                    float2 g11 = *(const float2*)(gp1 + k2);
                    x01.x += g01.x * invd0; x01.y += g01.y * invd0;
                    x11.x += g11.x * invd1; x11.y += g11.y * invd1;
                }
            }
            a[ks][0] = f2h2(x00.x, x00.y);
            a[ks][1] = f2h2(x10.x, x10.y);
            a[ks][2] = f2h2(x01.x, x01.y);
            a[ks][3] = f2h2(x11.x, x11.y);
        }
    }

    for (int nt = 0; nt < NT; nt++) {
        CP_WAIT0();
        __syncthreads();
        if (nt + 1 < NT) {
            const uint4* src = (const uint4*)(Bh + (size_t)(nt + 1) * TILE_U32);
            uint4* dst = (uint4*)(smu + ((nt + 1) & 1) * TILE_U32);
            #pragma unroll 13
            for (int i = tid; i < TILE_U32 / 4; i += 128) cpa16(dst + i, src + i);
            CP_COMMIT();
        }
        const uint2* B2 = (const uint2*)(smu + (nt & 1) * TILE_U32);

        float acc[8][4];
        #pragma unroll
        for (int ni = 0; ni < 8; ni++)
            #pragma unroll
            for (int q = 0; q < 4; q++) acc[ni][q] = 0.f;

        #pragma unroll
        for (int ks = 0; ks < KS16; ks++) {
            uint32_t b[8][2];
            #pragma unroll
            for (int ni = 0; ni < 8; ni++)
                *(uint2*)b[ni] = B2[(ks * 64 + ni * 8 + gid) * 4 + tig];
            #pragma unroll
            for (int ni = 0; ni < 8; ni++)
                mma16(acc[ni], a[ks], b[ni]);
        }

        // ---- epilogue: masked strided stores (full 64 cols) ----
        int n0 = nt * 64;
        int grow = row0 + wid * 16 + gid;
        #pragma unroll
        for (int ni = 0; ni < 8; ni++) {
            int gcol = n0 + ni * 8 + tig * 2;
            if (gcol < realN) {
                if (grow < M)
                    *(float2*)(Out + (size_t)grow * ostride + gcol) =
                        make_float2(acc[ni][0], acc[ni][1]);
                if (grow + 8 < M)
                    *(float2*)(Out + (size_t)(grow + 8) * ostride + gcol) =
                        make_float2(acc[ni][2], acc[ni][3]);
            }
        }
        __syncthreads();
    }
}

// ------- fused final: gate=sig(Graw+b); c2=L2raw+agg2/deg; h'=l2n(g*l2n(c2)+(1-g)h)
__global__ void final_kernel(const float* __restrict__ P1,
                             const float* __restrict__ bias,
                             const float* __restrict__ P2,
                             const float* __restrict__ agg2,
                             const float* __restrict__ deg,
                             const float* __restrict__ hin,
                             float* __restrict__ hout) {
    int warp = (blockIdx.x * blockDim.x + threadIdx.x) >> 5;
    int lane = threadIdx.x & 31;
    if (warp >= N_NODES) return;
    const float* graw = P1 + (size_t)warp * NP1 + 400;
    const float* l2r  = P2 + (size_t)warp * NP2 + 200;
    const float* ag   = agg2 + (size_t)warp * DIMV;
    const float* hp   = hin + (size_t)warp * DIMV;
    float invd = 1.f / fmaxf(deg[warp], 1.f);

    float cv[7], gv[7], hv[7];
    float s = 0.f;
    #pragma unroll
    for (int i = 0; i < 7; i++) {
        int j = lane + i * 32;
        float x = 0.f, g = 0.f, hh = 0.f;
        if (j < DIMV) {
            x  = l2r[j] + ag[j] * invd;
            g  = 1.f / (1.f + expf(-(graw[j] + bias[j])));
            hh = hp[j];
        }
        cv[i] = x; gv[i] = g; hv[i] = hh;
        s += x * x;
    }
    #pragma unroll
    for (int o = 16; o; o >>= 1) s += __shfl_xor_sync(0xffffffffu, s, o);
    float inv = 1.f / fmaxf(sqrtf(s), 1e-12f);

    float s2 = 0.f;
    #pragma unroll
    for (int i = 0; i < 7; i++) {
        float v = gv[i] * (cv[i] * inv) + (1.f - gv[i]) * hv[i];
        cv[i] = v;
        s2 += v * v;
    }
    #pragma unroll
    for (int o = 16; o; o >>= 1) s2 += __shfl_xor_sync(0xffffffffu, s2, o);
    float inv2 = 1.f / fmaxf(sqrtf(s2), 1e-12f);

    float* op = hout + (size_t)warp * DIMV;
    #pragma unroll
    for (int i = 0; i < 7; i++) {
        int j = lane + i * 32;
        if (j < DIMV) op[j] = cv[i] * inv2;
    }
}

// ---------------- host launcher --------------------------------------------
extern "C" void kernel_launch(void* const* d_in, const int* in_sizes, int n_in,
                              void* d_out, int out_size) {
    const int*   edges = (const int*)d_in[0];
    const float* ent   = (const float*)d_in[1];
    const float* rele  = (const float*)d_in[2];
    const float* Wm1   = (const float*)d_in[3];
    const float* Wl1   = (const float*)d_in[4];
    const float* Wm2   = (const float*)d_in[5];
    const float* Wl2   = (const float*)d_in[6];
    const float* Wg    = (const float*)d_in[7];
    const float* bg    = (const float*)d_in[8];
    float* out = (float*)d_out;

    float *h, *r, *P1, *P2, *agg1, *agg2, *rA1, *rA2, *deg;
    uint32_t *B1h, *B2h;
    cudaGetSymbolAddress((void**)&h,    g_h);
    cudaGetSymbolAddress((void**)&r,    g_r);
    cudaGetSymbolAddress((void**)&P1,   g_P1);
    cudaGetSymbolAddress((void**)&P2,   g_P2);
    cudaGetSymbolAddress((void**)&agg1, g_agg1);
    cudaGetSymbolAddress((void**)&agg2, g_agg2);
    cudaGetSymbolAddress((void**)&rA1,  g_rA1);
    cudaGetSymbolAddress((void**)&rA2,  g_rA2);
    cudaGetSymbolAddress((void**)&B1h,  g_B1h);
    cudaGetSymbolAddress((void**)&B2h,  g_B2h);
    cudaGetSymbolAddress((void**)&deg,  g_deg);

    cudaFuncSetAttribute((const void*)mma_gemm<0,0>, cudaFuncAttributeMaxDynamicSharedMemorySize, SMEMB);
    cudaFuncSetAttribute((const void*)mma_gemm<0,1>, cudaFuncAttributeMaxDynamicSharedMemorySize, SMEMB);
    cudaFuncSetAttribute((const void*)mma_gemm<1,0>, cudaFuncAttributeMaxDynamicSharedMemorySize, SMEMB);

    const int grid_m  = (N_NODES + BM - 1) / BM;  // 1563
    const int grid_mr = (N_RELS + BM - 1) / BM;   // 8

    // Launch order: big GEMM1 is launch index 3 (the one ncu profiles).
    l2norm_kernel<<<(N_NODES + 7) / 8, 256>>>(ent, h, N_NODES);                   // 0
    l2norm_kernel<<<(N_RELS + 7) / 8, 256>>>(rele, r, N_RELS);                    // 1
    packB1h_kernel<<<(NT1 * TILE_U32 + 255) / 256, 256>>>(Wm1, Wl1, Wg, B1h);     // 2
    // 3: BIG GEMM1 of t=0 (profiled) — also zeroes agg1/agg2/deg for t=0
    mma_gemm<0,1><<<grid_m, 128, SMEMB>>>(h, DIMV, nullptr, nullptr, B1h,
                                          P1, NP1, 600, N_NODES, NT1,
                                          agg1, agg2, deg);
    packB2h_kernel<<<(NT2 * TILE_U32 + 255) / 256, 256>>>(Wm2, Wl2, B2h);         // 4
    // time-invariant relation projections (first 200 packed cols)
    mma_gemm<0,0><<<grid_mr, 128, SMEMB>>>(r, DIMV, nullptr, nullptr, B1h,
                                           rA1, DIMV, 200, N_RELS, 4,
                                           nullptr, nullptr, nullptr);
    mma_gemm<0,0><<<grid_mr, 128, SMEMB>>>(r, DIMV, nullptr, nullptr, B2h,
                                           rA2, DIMV, 200, N_RELS, 4,
                                           nullptr, nullptr, nullptr);

    for (int t = 0; t < 3; t++) {
        const int* e = edges + (size_t)t * N_EDG * 3;

        if (t > 0)
            mma_gemm<0,1><<<grid_m, 128, SMEMB>>>(h, DIMV, nullptr, nullptr, B1h,
                                                  P1, NP1, 600, N_NODES, NT1,
                                                  agg1, agg2, deg);
        scatter_kernel<<<(N_EDG + 7) / 8, 256>>>(e, P1, NP1, rA1, agg1, deg);

        mma_gemm<1,0><<<grid_m, 128, SMEMB>>>(P1 + 200, NP1, agg1, deg, B2h,
                                              P2, NP2, 400, N_NODES, NT2,
                                              nullptr, nullptr, nullptr);
        scatter_kernel<<<(N_EDG + 7) / 8, 256>>>(e, P2, NP2, rA2, agg2, nullptr);

        final_kernel<<<(N_NODES + 7) / 8, 256>>>(P1, bg, P2, agg2, deg, h,
                                                 (t == 2) ? out : h);
    }
}